// round 2
// baseline (speedup 1.0000x reference)
#include <cuda_runtime.h>
#include <math.h>

#define NN 50000
#define NE 800000
#define C 128

// Scratch (device globals; no allocation allowed)
__device__ float g_M1[C * C];
__device__ float g_M2[C * C];
__device__ float g_M3[C * C];
__device__ float g_cb[C];
__device__ float g_A[NN * C];
__device__ float g_B[NN * C];

// ---------------------------------------------------------------------------
// K1: fold the three input linears through enc_W.
// M1 = node_W @ enc_W[0:128,:], M2 = nbr_W @ enc_W[128:256,:], M3 = gud_W @ enc_W[256:384,:]
// ---------------------------------------------------------------------------
__global__ void fold_kernel(const float* __restrict__ node_W,
                            const float* __restrict__ nbr_W,
                            const float* __restrict__ gud_W,
                            const float* __restrict__ enc_W) {
    int m = blockIdx.y;
    const float* W = (m == 0) ? node_W : ((m == 1) ? nbr_W : gud_W);
    const float* E = enc_W + m * C * C;
    float* M = (m == 0) ? g_M1 : ((m == 1) ? g_M2 : g_M3);

    int j = threadIdx.x & 127;
    int iq = threadIdx.x >> 7;  // 0..1
    int i0 = blockIdx.x * 32;
    for (int i = i0 + iq; i < i0 + 32; i += 2) {
        float s = 0.f;
#pragma unroll 4
        for (int h = 0; h < C; h++) s += W[i * C + h] * E[h * C + j];
        M[i * C + j] = s;
    }
}

// cbias[j] = enc_b[j] + sum_h node_b[h]*E[h][j] + nbr_b[h]*E[128+h][j] + gud_b[h]*E[256+h][j]
__global__ void cb_kernel(const float* __restrict__ node_b,
                          const float* __restrict__ nbr_b,
                          const float* __restrict__ gud_b,
                          const float* __restrict__ enc_W,
                          const float* __restrict__ enc_b) {
    int j = threadIdx.x;
    float s = enc_b[j];
    for (int h = 0; h < C; h++) s += node_b[h] * enc_W[h * C + j];
    for (int h = 0; h < C; h++) s += nbr_b[h] * enc_W[(C + h) * C + j];
    for (int h = 0; h < C; h++) s += gud_b[h] * enc_W[(2 * C + h) * C + j];
    g_cb[j] = s;
}

// ---------------------------------------------------------------------------
// K2: per-node precompute. grid (782, 2).
//   y==0: A = x @ M1          [NN,128]
//   y==1: B = x @ M2 + g @ M3 [NN,128]
// ---------------------------------------------------------------------------
__global__ __launch_bounds__(256, 2)
void node_gemm_kernel(const float* __restrict__ x, const float* __restrict__ g) {
    extern __shared__ float sm[];
    float* Ws = sm;            // 128*128
    float* Xs = sm + C * C;    // 64*128

    int tx = threadIdx.x & 31, ty = threadIdx.x >> 5;  // 8 warps
    int m0 = blockIdx.x * 64;
    bool doB = (blockIdx.y == 1);

    float acc[8][4];
#pragma unroll
    for (int a = 0; a < 8; a++)
#pragma unroll
        for (int b = 0; b < 4; b++) acc[a][b] = 0.f;

    int phases = doB ? 2 : 1;
    for (int ph = 0; ph < phases; ph++) {
        const float* M = doB ? ((ph == 0) ? g_M2 : g_M3) : g_M1;
        const float* src = (doB && ph == 1) ? g : x;
        if (ph) __syncthreads();

        // Stage weights
        {
            const float4* m4 = (const float4*)M;
            float4* w4 = (float4*)Ws;
            for (int idx = threadIdx.x; idx < C * C / 4; idx += blockDim.x)
                w4[idx] = m4[idx];
        }
        // Stage node rows (zero-pad past NN)
        for (int r = ty; r < 64; r += 8) {
            int n = m0 + r;
            float4 v = make_float4(0.f, 0.f, 0.f, 0.f);
            if (n < NN) v = ((const float4*)(src + (long)n * C))[tx];
            ((float4*)(Xs + r * C))[tx] = v;
        }
        __syncthreads();

        for (int k = 0; k < C; k += 4) {
            float4 z[8];
#pragma unroll
            for (int im = 0; im < 8; im++)
                z[im] = *(const float4*)&Xs[(ty * 8 + im) * C + k];
#pragma unroll
            for (int kk = 0; kk < 4; kk++) {
                float w[4];
#pragma unroll
                for (int in = 0; in < 4; in++) w[in] = Ws[(k + kk) * C + tx + 32 * in];
#pragma unroll
                for (int im = 0; im < 8; im++) {
                    float zv = ((const float*)&z[im])[kk];
#pragma unroll
                    for (int in = 0; in < 4; in++) acc[im][in] += zv * w[in];
                }
            }
        }
    }

    float* dst = doB ? g_B : g_A;
#pragma unroll
    for (int im = 0; im < 8; im++) {
        int n = m0 + ty * 8 + im;
        if (n < NN) {
#pragma unroll
            for (int in = 0; in < 4; in++)
                dst[(long)n * C + tx + 32 * in] = acc[im][in];
        }
    }
}

// ---------------------------------------------------------------------------
// K3: per-edge fused GEMM + heads. Persistent grid, 512 threads (16 warps),
// tile 128 edges. Z rows are warp-private; only __syncwarp in main loop.
// Thread tile 8(M) x 6(N); N=192 = [vp_W1 (64) | pol_W1 (128)].
// edge_index is int32 (JAX default x64-disabled downcasts int64 -> int32).
// ---------------------------------------------------------------------------
__global__ __launch_bounds__(512, 1)
void edge_kernel(const int* __restrict__ ei,
                 const float* __restrict__ vp_W1, const float* __restrict__ vp_b1,
                 const float* __restrict__ vp_W2, const float* __restrict__ vp_b2,
                 const float* __restrict__ pol_W1, const float* __restrict__ pol_b1,
                 const float* __restrict__ pol_W2, const float* __restrict__ pol_b2,
                 float* __restrict__ out) {
    extern __shared__ float sm[];
    float* Ws = sm;             // [128][192]
    float* Zs = sm + C * 192;   // [128][128]

    int tx = threadIdx.x & 31, ty = threadIdx.x >> 5;  // 16 warps

    // Stage fused weight matrix [128][192]
    for (int idx = threadIdx.x; idx < C * 192; idx += blockDim.x) {
        int k = idx / 192, n = idx % 192;
        Ws[idx] = (n < 64) ? vp_W1[k * 64 + n] : pol_W1[k * C + (n - 64)];
    }

    // Per-thread epilogue constants
    float vb[2], vw[2], pb[4], pw[4];
#pragma unroll
    for (int in = 0; in < 2; in++) {
        vb[in] = vp_b1[tx + 32 * in];
        vw[in] = vp_W2[tx + 32 * in];
    }
#pragma unroll
    for (int in = 0; in < 4; in++) {
        pb[in] = pol_b1[tx + 32 * in];
        pw[in] = pol_W2[tx + 32 * in];
    }
    float vb2 = vp_b2[0], pb2 = pol_b2[0];
    float4 cb4 = ((const float4*)g_cb)[tx];
    __syncthreads();

    if (blockIdx.x == 0 && threadIdx.x == 0) out[3L * NE] = 0.f;  // value_loss

    const int ntiles = NE / 128;  // 6250 exact
    for (int t = blockIdx.x; t < ntiles; t += gridDim.x) {
        long base = (long)t * 128;

        __syncwarp();  // prior k-loop reads of our Zs rows are done
#pragma unroll
        for (int i = 0; i < 8; i++) {
            int m = ty * 8 + i;
            long e = base + m;
            int r = ei[e];
            int c = ei[NE + e];
            float4 a = ((const float4*)(g_A + (long)r * C))[tx];
            float4 b = ((const float4*)(g_B + (long)c * C))[tx];
            float4 z;
            z.x = fmaxf(a.x + b.x + cb4.x, 0.f);
            z.y = fmaxf(a.y + b.y + cb4.y, 0.f);
            z.z = fmaxf(a.z + b.z + cb4.z, 0.f);
            z.w = fmaxf(a.w + b.w + cb4.w, 0.f);
            ((float4*)(Zs + m * C))[tx] = z;
        }
        __syncwarp();

        float acc[8][6];
#pragma unroll
        for (int a = 0; a < 8; a++)
#pragma unroll
            for (int b = 0; b < 6; b++) acc[a][b] = 0.f;

        for (int k = 0; k < C; k += 4) {
            float4 z[8];
#pragma unroll
            for (int im = 0; im < 8; im++)
                z[im] = *(const float4*)&Zs[(ty * 8 + im) * C + k];
#pragma unroll
            for (int kk = 0; kk < 4; kk++) {
                float w[6];
#pragma unroll
                for (int in = 0; in < 6; in++)
                    w[in] = Ws[(k + kk) * 192 + tx + 32 * in];
#pragma unroll
                for (int im = 0; im < 8; im++) {
                    float zv = ((const float*)&z[im])[kk];
#pragma unroll
                    for (int in = 0; in < 6; in++) acc[im][in] += zv * w[in];
                }
            }
        }

        // Epilogue: heads + warp reduction
#pragma unroll
        for (int im = 0; im < 8; im++) {
            float vp = 0.f, lp = 0.f;
#pragma unroll
            for (int in = 0; in < 2; in++)
                vp += fmaxf(acc[im][in] + vb[in], 0.f) * vw[in];
#pragma unroll
            for (int in = 0; in < 4; in++)
                lp += fmaxf(acc[im][2 + in] + pb[in], 0.f) * pw[in];
#pragma unroll
            for (int off = 16; off; off >>= 1) {
                vp += __shfl_down_sync(0xffffffffu, vp, off);
                lp += __shfl_down_sync(0xffffffffu, lp, off);
            }
            if (tx == 0) {
                long e = base + ty * 8 + im;
                float v = vp + vb2;
                float logit = lp + pb2;
                float p = 1.f / (1.f + expf(-logit));
                out[e] = v;
                out[NE + e] = p;
                out[2L * NE + e] = (p > 0.5f) ? 1.f : 0.f;
            }
        }
    }
}

// ---------------------------------------------------------------------------
extern "C" void kernel_launch(void* const* d_in, const int* in_sizes, int n_in,
                              void* d_out, int out_size) {
    const float* x       = (const float*)d_in[0];
    const int*   ei      = (const int*)d_in[1];
    const float* gf      = (const float*)d_in[2];
    const float* node_W  = (const float*)d_in[3];
    const float* node_b  = (const float*)d_in[4];
    const float* nbr_W   = (const float*)d_in[5];
    const float* nbr_b   = (const float*)d_in[6];
    const float* gud_W   = (const float*)d_in[7];
    const float* gud_b   = (const float*)d_in[8];
    const float* enc_W   = (const float*)d_in[9];
    const float* enc_b   = (const float*)d_in[10];
    const float* vp_W1   = (const float*)d_in[11];
    const float* vp_b1   = (const float*)d_in[12];
    const float* vp_W2   = (const float*)d_in[13];
    const float* vp_b2   = (const float*)d_in[14];
    const float* pol_W1  = (const float*)d_in[15];
    const float* pol_b1  = (const float*)d_in[16];
    const float* pol_W2  = (const float*)d_in[17];
    const float* pol_b2  = (const float*)d_in[18];
    float* out = (float*)d_out;

    fold_kernel<<<dim3(4, 3), 256>>>(node_W, nbr_W, gud_W, enc_W);
    cb_kernel<<<1, 128>>>(node_b, nbr_b, gud_b, enc_W, enc_b);

    size_t smem2 = (size_t)(C * C + 64 * C) * sizeof(float);  // 96KB
    cudaFuncSetAttribute(node_gemm_kernel,
                         cudaFuncAttributeMaxDynamicSharedMemorySize, (int)smem2);
    node_gemm_kernel<<<dim3((NN + 63) / 64, 2), 256, smem2>>>(x, gf);

    size_t smem3 = (size_t)(C * 192 + 128 * C) * sizeof(float);  // 160KB
    cudaFuncSetAttribute(edge_kernel,
                         cudaFuncAttributeMaxDynamicSharedMemorySize, (int)smem3);
    edge_kernel<<<152, 512, smem3>>>(ei, vp_W1, vp_b1, vp_W2, vp_b2,
                                     pol_W1, pol_b1, pol_W2, pol_b2, out);
}

// round 4
// speedup vs baseline: 2.1003x; 2.1003x over previous
#include <cuda_runtime.h>
#include <cuda_bf16.h>
#include <math.h>
#include <stdint.h>

#define NN 50000
#define NE 800000
#define C 128

// Scratch (device globals; no allocation allowed)
__device__ float g_M1[C * C];
__device__ float g_M2[C * C];
__device__ float g_M3[C * C];
__device__ float g_cb[C];
__device__ float g_A[NN * C];
__device__ float g_B[NN * C];

__device__ __forceinline__ uint32_t smem_u32(const void* p) {
    uint32_t a;
    asm("{ .reg .u64 t; cvta.to.shared.u64 t, %1; cvt.u32.u64 %0, t; }"
        : "=r"(a) : "l"(p));
    return a;
}
__device__ __forceinline__ void ldsm_x4(uint32_t* r, uint32_t addr) {
    asm volatile("ldmatrix.sync.aligned.m8n8.x4.shared.b16 {%0,%1,%2,%3}, [%4];"
                 : "=r"(r[0]), "=r"(r[1]), "=r"(r[2]), "=r"(r[3]) : "r"(addr));
}
__device__ __forceinline__ void mma_bf16(float* c, const uint32_t* a,
                                         uint32_t b0, uint32_t b1) {
    asm volatile(
        "mma.sync.aligned.m16n8k16.row.col.f32.bf16.bf16.f32 "
        "{%0,%1,%2,%3}, {%4,%5,%6,%7}, {%8,%9}, {%0,%1,%2,%3};"
        : "+f"(c[0]), "+f"(c[1]), "+f"(c[2]), "+f"(c[3])
        : "r"(a[0]), "r"(a[1]), "r"(a[2]), "r"(a[3]), "r"(b0), "r"(b1));
}

// ---------------------------------------------------------------------------
// K1: fold the three input linears through enc_W.
// ---------------------------------------------------------------------------
__global__ void fold_kernel(const float* __restrict__ node_W,
                            const float* __restrict__ nbr_W,
                            const float* __restrict__ gud_W,
                            const float* __restrict__ enc_W) {
    int m = blockIdx.y;
    const float* W = (m == 0) ? node_W : ((m == 1) ? nbr_W : gud_W);
    const float* E = enc_W + m * C * C;
    float* M = (m == 0) ? g_M1 : ((m == 1) ? g_M2 : g_M3);

    int j = threadIdx.x & 127;
    int iq = threadIdx.x >> 7;
    int i0 = blockIdx.x * 32;
    for (int i = i0 + iq; i < i0 + 32; i += 2) {
        float s = 0.f;
#pragma unroll 4
        for (int h = 0; h < C; h++) s += W[i * C + h] * E[h * C + j];
        M[i * C + j] = s;
    }
}

__global__ void cb_kernel(const float* __restrict__ node_b,
                          const float* __restrict__ nbr_b,
                          const float* __restrict__ gud_b,
                          const float* __restrict__ enc_W,
                          const float* __restrict__ enc_b) {
    int j = threadIdx.x;
    float s = enc_b[j];
    for (int h = 0; h < C; h++) s += node_b[h] * enc_W[h * C + j];
    for (int h = 0; h < C; h++) s += nbr_b[h] * enc_W[(C + h) * C + j];
    for (int h = 0; h < C; h++) s += gud_b[h] * enc_W[(2 * C + h) * C + j];
    g_cb[j] = s;
}

// ---------------------------------------------------------------------------
// K2: per-node precompute (FFMA).
// ---------------------------------------------------------------------------
__global__ __launch_bounds__(256, 2)
void node_gemm_kernel(const float* __restrict__ x, const float* __restrict__ g) {
    extern __shared__ float sm[];
    float* Ws = sm;
    float* Xs = sm + C * C;

    int tx = threadIdx.x & 31, ty = threadIdx.x >> 5;
    int m0 = blockIdx.x * 64;
    bool doB = (blockIdx.y == 1);

    float acc[8][4];
#pragma unroll
    for (int a = 0; a < 8; a++)
#pragma unroll
        for (int b = 0; b < 4; b++) acc[a][b] = 0.f;

    int phases = doB ? 2 : 1;
    for (int ph = 0; ph < phases; ph++) {
        const float* M = doB ? ((ph == 0) ? g_M2 : g_M3) : g_M1;
        const float* src = (doB && ph == 1) ? g : x;
        if (ph) __syncthreads();

        {
            const float4* m4 = (const float4*)M;
            float4* w4 = (float4*)Ws;
            for (int idx = threadIdx.x; idx < C * C / 4; idx += blockDim.x)
                w4[idx] = m4[idx];
        }
        for (int r = ty; r < 64; r += 8) {
            int n = m0 + r;
            float4 v = make_float4(0.f, 0.f, 0.f, 0.f);
            if (n < NN) v = ((const float4*)(src + (long)n * C))[tx];
            ((float4*)(Xs + r * C))[tx] = v;
        }
        __syncthreads();

        for (int k = 0; k < C; k += 4) {
            float4 z[8];
#pragma unroll
            for (int im = 0; im < 8; im++)
                z[im] = *(const float4*)&Xs[(ty * 8 + im) * C + k];
#pragma unroll
            for (int kk = 0; kk < 4; kk++) {
                float w[4];
#pragma unroll
                for (int in = 0; in < 4; in++) w[in] = Ws[(k + kk) * C + tx + 32 * in];
#pragma unroll
                for (int im = 0; im < 8; im++) {
                    float zv = ((const float*)&z[im])[kk];
#pragma unroll
                    for (int in = 0; in < 4; in++) acc[im][in] += zv * w[in];
                }
            }
        }
    }

    float* dst = doB ? g_B : g_A;
#pragma unroll
    for (int im = 0; im < 8; im++) {
        int n = m0 + ty * 8 + im;
        if (n < NN) {
#pragma unroll
            for (int in = 0; in < 4; in++)
                dst[(long)n * C + tx + 32 * in] = acc[im][in];
        }
    }
}

// ---------------------------------------------------------------------------
// K3: split-bf16 edge kernel via mma.sync (HMMA tensor path, portable PTX).
// SMEM (bytes):
//   [0..1536)        params: vb1[64] vw2[64] pb1[128] pw2[128] (floats)
//   [2048..71680)    A: 8 warps x (hi 16x272B + lo 16x272B) = 8704 B/warp
//   [71680..123904)  B hi: 192 rows x 272 B
//   [123904..176128) B lo
// Row pitch 272 B keeps ldmatrix conflict-free (+4 banks/row).
// ---------------------------------------------------------------------------
#define PITCH    272
#define A_OFF    2048
#define A_WARP   (2 * 16 * PITCH)          // 8704
#define B_H_OFF  (A_OFF + 8 * A_WARP)      // 71680
#define B_L_OFF  (B_H_OFF + 192 * PITCH)   // 123904
#define SMEM_E   (B_L_OFF + 192 * PITCH)   // 176128
#define NGRID    148

__global__ __launch_bounds__(256, 1)
void edge_kernel_mma(const int* __restrict__ ei,
                     const float* __restrict__ vp_W1, const float* __restrict__ vp_b1,
                     const float* __restrict__ vp_W2, const float* __restrict__ vp_b2,
                     const float* __restrict__ pol_W1, const float* __restrict__ pol_b1,
                     const float* __restrict__ pol_W2, const float* __restrict__ pol_b2,
                     float* __restrict__ out) {
    extern __shared__ float smf[];
    char* smc = (char*)smf;
    uint32_t su = smem_u32(smf);
    int tid = threadIdx.x;
    int tx = tid & 31, wid = tid >> 5;

    // --- stage split weights B[n][k], n<64: vp_W1, else pol_W1 ---
    for (int idx = tid; idx < 192 * C; idx += 256) {
        int n = idx >> 7, k = idx & 127;
        float w = (n < 64) ? vp_W1[k * 64 + n] : pol_W1[k * C + (n - 64)];
        __nv_bfloat16 wh = __float2bfloat16(w);
        __nv_bfloat16 wl = __float2bfloat16(w - __bfloat162float(wh));
        *(__nv_bfloat16*)(smc + B_H_OFF + n * PITCH + k * 2) = wh;
        *(__nv_bfloat16*)(smc + B_L_OFF + n * PITCH + k * 2) = wl;
    }
    // --- stage epilogue params ---
    if (tid < 64) { smf[tid] = vp_b1[tid]; smf[64 + tid] = vp_W2[tid]; }
    if (tid < 128) { smf[128 + tid] = pol_b1[tid]; smf[256 + tid] = pol_W2[tid]; }
    __syncthreads();

    float vb2v = vp_b2[0], pb2v = pol_b2[0];
    float4 cb4 = ((const float4*)g_cb)[tx];
    if (blockIdx.x == 0 && tid == 0) out[3L * NE] = 0.f;  // value_loss

    uint32_t awu = su + A_OFF + wid * A_WARP;   // this warp's A hi base
    // ldmatrix lane addressing
    uint32_t a_row = (tx & 7) + 8 * ((tx >> 3) & 1);
    uint32_t a_k16 = (tx >> 4) * 16;
    uint32_t b_row = (tx & 7) + 8 * (tx >> 4);
    uint32_t b_k16 = ((tx >> 3) & 1) * 16;

    const int ntiles = NE / 128;  // 6250
    for (int t = blockIdx.x; t < ntiles; t += NGRID) {
        long base = (long)t * 128 + wid * 16;

        __syncwarp();
        // ---- gather 16 edges -> split-bf16 A (warp-private region) ----
#pragma unroll 4
        for (int m = 0; m < 16; m++) {
            int rr = ei[base + m];
            int cc = ei[NE + base + m];
            float4 a = ((const float4*)(g_A + (size_t)rr * C))[tx];
            float4 b = ((const float4*)(g_B + (size_t)cc * C))[tx];
            float z0 = fmaxf(a.x + b.x + cb4.x, 0.f);
            float z1 = fmaxf(a.y + b.y + cb4.y, 0.f);
            float z2 = fmaxf(a.z + b.z + cb4.z, 0.f);
            float z3 = fmaxf(a.w + b.w + cb4.w, 0.f);
            __nv_bfloat162 h01 = __floats2bfloat162_rn(z0, z1);
            __nv_bfloat162 h23 = __floats2bfloat162_rn(z2, z3);
            __nv_bfloat162 l01 = __floats2bfloat162_rn(
                z0 - __bfloat162float(h01.x), z1 - __bfloat162float(h01.y));
            __nv_bfloat162 l23 = __floats2bfloat162_rn(
                z2 - __bfloat162float(h23.x), z3 - __bfloat162float(h23.y));
            uint2 hv, lv;
            hv.x = *(uint32_t*)&h01; hv.y = *(uint32_t*)&h23;
            lv.x = *(uint32_t*)&l01; lv.y = *(uint32_t*)&l23;
            *(uint2*)(smc + (awu - su) + m * PITCH + tx * 8) = hv;
            *(uint2*)(smc + (awu - su) + 16 * PITCH + m * PITCH + tx * 8) = lv;
        }
        __syncwarp();

        // ---- MMA: [16 x 128] x [128 x 192] split-bf16, fp32 accum ----
        float acc[24][4];
#pragma unroll
        for (int a = 0; a < 24; a++)
#pragma unroll
            for (int b = 0; b < 4; b++) acc[a][b] = 0.f;

        for (int ks = 0; ks < 8; ks++) {
            uint32_t ah[4], al[4];
            uint32_t acol = ks * 32 + a_k16;
            ldsm_x4(ah, awu + a_row * PITCH + acol);
            ldsm_x4(al, awu + 16 * PITCH + a_row * PITCH + acol);
            uint32_t bcol = ks * 32 + b_k16;
#pragma unroll
            for (int np = 0; np < 12; np++) {
                uint32_t bro = (np * 16 + b_row) * PITCH + bcol;
                uint32_t bh[4], bl[4];
                ldsm_x4(bh, su + B_H_OFF + bro);
                ldsm_x4(bl, su + B_L_OFF + bro);
                mma_bf16(acc[2 * np], ah, bh[0], bh[1]);
                mma_bf16(acc[2 * np], al, bh[0], bh[1]);
                mma_bf16(acc[2 * np], ah, bl[0], bl[1]);
                mma_bf16(acc[2 * np + 1], ah, bh[2], bh[3]);
                mma_bf16(acc[2 * np + 1], al, bh[2], bh[3]);
                mma_bf16(acc[2 * np + 1], ah, bl[2], bl[3]);
            }
        }

        // ---- epilogue: heads from C-fragment layout ----
        float vr = 0.f, vr8 = 0.f, lr = 0.f, lr8 = 0.f;
#pragma unroll
        for (int nt = 0; nt < 24; nt++) {
            int c0 = nt * 8 + 2 * (tx & 3);
            if (nt < 8) {
                float b0 = smf[c0], w0 = smf[64 + c0];
                float b1 = smf[c0 + 1], w1 = smf[64 + c0 + 1];
                vr  += fmaxf(acc[nt][0] + b0, 0.f) * w0 + fmaxf(acc[nt][1] + b1, 0.f) * w1;
                vr8 += fmaxf(acc[nt][2] + b0, 0.f) * w0 + fmaxf(acc[nt][3] + b1, 0.f) * w1;
            } else {
                int ix = c0 - 64;
                float b0 = smf[128 + ix], w0 = smf[256 + ix];
                float b1 = smf[128 + ix + 1], w1 = smf[256 + ix + 1];
                lr  += fmaxf(acc[nt][0] + b0, 0.f) * w0 + fmaxf(acc[nt][1] + b1, 0.f) * w1;
                lr8 += fmaxf(acc[nt][2] + b0, 0.f) * w0 + fmaxf(acc[nt][3] + b1, 0.f) * w1;
            }
        }
#pragma unroll
        for (int off = 1; off <= 2; off <<= 1) {
            vr  += __shfl_xor_sync(0xffffffffu, vr, off);
            vr8 += __shfl_xor_sync(0xffffffffu, vr8, off);
            lr  += __shfl_xor_sync(0xffffffffu, lr, off);
            lr8 += __shfl_xor_sync(0xffffffffu, lr8, off);
        }
        if ((tx & 3) == 0) {
            int r = tx >> 2;
            long e0 = base + r;
            long e1 = base + r + 8;
            float v0 = vr + vb2v, v1 = vr8 + vb2v;
            float p0 = 1.f / (1.f + expf(-(lr + pb2v)));
            float p1 = 1.f / (1.f + expf(-(lr8 + pb2v)));
            out[e0] = v0;
            out[e1] = v1;
            out[NE + e0] = p0;
            out[NE + e1] = p1;
            out[2L * NE + e0] = (p0 > 0.5f) ? 1.f : 0.f;
            out[2L * NE + e1] = (p1 > 0.5f) ? 1.f : 0.f;
        }
    }
}

// ---------------------------------------------------------------------------
extern "C" void kernel_launch(void* const* d_in, const int* in_sizes, int n_in,
                              void* d_out, int out_size) {
    const float* x       = (const float*)d_in[0];
    const int*   ei      = (const int*)d_in[1];
    const float* gf      = (const float*)d_in[2];
    const float* node_W  = (const float*)d_in[3];
    const float* node_b  = (const float*)d_in[4];
    const float* nbr_W   = (const float*)d_in[5];
    const float* nbr_b   = (const float*)d_in[6];
    const float* gud_W   = (const float*)d_in[7];
    const float* gud_b   = (const float*)d_in[8];
    const float* enc_W   = (const float*)d_in[9];
    const float* enc_b   = (const float*)d_in[10];
    const float* vp_W1   = (const float*)d_in[11];
    const float* vp_b1   = (const float*)d_in[12];
    const float* vp_W2   = (const float*)d_in[13];
    const float* vp_b2   = (const float*)d_in[14];
    const float* pol_W1  = (const float*)d_in[15];
    const float* pol_b1  = (const float*)d_in[16];
    const float* pol_W2  = (const float*)d_in[17];
    const float* pol_b2  = (const float*)d_in[18];
    float* out = (float*)d_out;

    fold_kernel<<<dim3(4, 3), 256>>>(node_W, nbr_W, gud_W, enc_W);
    cb_kernel<<<1, 128>>>(node_b, nbr_b, gud_b, enc_W, enc_b);

    size_t smem2 = (size_t)(C * C + 64 * C) * sizeof(float);
    cudaFuncSetAttribute(node_gemm_kernel,
                         cudaFuncAttributeMaxDynamicSharedMemorySize, (int)smem2);
    node_gemm_kernel<<<dim3((NN + 63) / 64, 2), 256, smem2>>>(x, gf);

    cudaFuncSetAttribute(edge_kernel_mma,
                         cudaFuncAttributeMaxDynamicSharedMemorySize, SMEM_E);
    edge_kernel_mma<<<NGRID, 256, SMEM_E>>>(ei, vp_W1, vp_b1, vp_W2, vp_b2,
                                            pol_W1, pol_b1, pol_W2, pol_b2, out);
}